// round 12
// baseline (speedup 1.0000x reference)
#include <cuda_runtime.h>

// B=8, MSP=2048, D=512, A=64, NB=5
// Exact contraction reordering:
//   Wc[n,d]   = W_fl[n,d] + W_fl[n,512+d]
//   S[n]      = sum_d Wc[n,d]
//   t[b,s,n]  = sum_d e[b,s,d] * Wc[n,d]
//   out[b,a,n]= sum_s W_ll[a,s] * t[b,s,n] + b_ll[a]*S[n] + b_fl[n]
//   final[b,i,j,n] = out[b,i,n]
//
// R5 split structure (best measured) with a rebuilt t_kernel:
//  - Wc read from smem per row (regs ~60) -> 4 blocks/SM, 32 warps/SM.
//  - Static double-buffered loads (evA/evB, distance-2): ~2 rows in
//    flight per warp at all times. No dynamic register indexing.

#define NROWS  16384      // B * MSP
#define DVAL   512
#define NB     5
#define AVAL   64
#define BVAL   8
#define MSP    2048
#define K1GRID 592        // 4 blocks/SM x 148 SMs
#define NW     (K1GRID * 8)

__device__ float g_S[NB];
__device__ float g_t[NROWS * NB];          // 320 KB scratch (L2-resident)

// ---------------------------------------------------------------------------
// Kernel 1: t[b,s,n]. 592 blocks x 256 threads, 4 blocks/SM.
// ---------------------------------------------------------------------------
__global__ __launch_bounds__(256, 4) void t_kernel(const float* __restrict__ e,
                                                   const float* __restrict__ W_fl) {
    __shared__ __align__(16) float wcs[NB * DVAL];   // 10 KB
    const int tid  = threadIdx.x;
    const int lane = tid & 31;
    const int warp = tid >> 5;

    for (int i = tid; i < NB * DVAL; i += 256) {
        int n = i / DVAL, d = i - n * DVAL;
        wcs[i] = W_fl[n * 1024 + d] + W_fl[n * 1024 + 512 + d];
    }
    __syncthreads();

    if (blockIdx.x == 0 && warp == 0) {
        #pragma unroll
        for (int n = 0; n < NB; n++) {
            float s = 0.f;
            for (int d = lane; d < DVAL; d += 32) s += wcs[n * DVAL + d];
            #pragma unroll
            for (int off = 16; off > 0; off >>= 1)
                s += __shfl_xor_sync(0xFFFFFFFFu, s, off);
            if (lane == 0) g_S[n] = s;
        }
    }

    const int gw = blockIdx.x * 8 + warp;

    // Load macro: 4 front-batched LDG.128 for one row into a static buffer
    #define LOADROW(EV, ROW)                                                   \
        do {                                                                   \
            const float4* er_ = (const float4*)(e + (size_t)(ROW) * DVAL);     \
            EV[0] = er_[lane];                                                 \
            EV[1] = er_[32 + lane];                                            \
            EV[2] = er_[64 + lane];                                            \
            EV[3] = er_[96 + lane];                                            \
        } while (0)

    // Process macro: Wc from smem (conflict-free LDS.128), butterfly, store
    #define PROCROW(EV, ROW)                                                   \
        do {                                                                   \
            float acc_[NB];                                                    \
            _Pragma("unroll")                                                  \
            for (int n_ = 0; n_ < NB; n_++) acc_[n_] = 0.f;                    \
            _Pragma("unroll")                                                  \
            for (int r_ = 0; r_ < 4; r_++) {                                   \
                _Pragma("unroll")                                              \
                for (int n_ = 0; n_ < NB; n_++) {                              \
                    float4 w_ = *(const float4*)&wcs[n_ * DVAL + r_ * 128 + lane * 4]; \
                    acc_[n_] += EV[r_].x * w_.x + EV[r_].y * w_.y              \
                              + EV[r_].z * w_.z + EV[r_].w * w_.w;             \
                }                                                              \
            }                                                                  \
            _Pragma("unroll")                                                  \
            for (int n_ = 0; n_ < NB; n_++) {                                  \
                _Pragma("unroll")                                              \
                for (int off_ = 16; off_ > 0; off_ >>= 1)                      \
                    acc_[n_] += __shfl_xor_sync(0xFFFFFFFFu, acc_[n_], off_);  \
            }                                                                  \
            if (lane == 0) {                                                   \
                float* tp_ = &g_t[(ROW) * NB];                                 \
                _Pragma("unroll")                                              \
                for (int n_ = 0; n_ < NB; n_++) tp_[n_] = acc_[n_];            \
            }                                                                  \
        } while (0)

    float4 evA[4], evB[4];
    int rowA = gw;
    int rowB = gw + NW;
    if (rowA < NROWS) LOADROW(evA, rowA);
    if (rowB < NROWS) LOADROW(evB, rowB);

    while (rowA < NROWS) {
        // Consume A's FFMAs, then immediately refill A (2 rows in flight
        // through A's butterfly tail and B's processing).
        {
            const int pre = rowA + 2 * NW;
            PROCROW(evA, rowA);
            if (pre < NROWS) LOADROW(evA, pre);
            rowA = pre;
        }
        if (rowB < NROWS) {
            const int pre = rowB + 2 * NW;
            PROCROW(evB, rowB);
            if (pre < NROWS) LOADROW(evB, pre);
            rowB = pre;
        }
    }
    #undef LOADROW
    #undef PROCROW
}

// ---------------------------------------------------------------------------
// Kernel 2: out[b,a,n] + broadcast over j (R5 verbatim — best measured).
// grid = (64 a, 8 b) = 512 blocks, 256 threads.
// ---------------------------------------------------------------------------
__global__ __launch_bounds__(256) void out_kernel(const float* __restrict__ W_ll,
                                                  const float* __restrict__ b_ll,
                                                  const float* __restrict__ b_fl,
                                                  float* __restrict__ out) {
    __shared__ float partial[8 * NB];
    __shared__ float v[NB];
    const int a    = blockIdx.x;
    const int b    = blockIdx.y;
    const int tid  = threadIdx.x;
    const int lane = tid & 31;
    const int w    = tid >> 5;

    const float* wrow  = W_ll + (size_t)a * MSP + w * 256;
    const float* tbase = g_t + ((size_t)b * MSP + w * 256) * NB;

    float wv[8];
    #pragma unroll
    for (int k = 0; k < 8; k++) wv[k] = wrow[lane + 32 * k];

    float a0 = 0.f, a1 = 0.f, a2 = 0.f, a3 = 0.f, a4 = 0.f;
    #pragma unroll
    for (int k = 0; k < 8; k++) {
        const float* tp = &tbase[(lane + 32 * k) * NB];
        a0 += wv[k] * tp[0];
        a1 += wv[k] * tp[1];
        a2 += wv[k] * tp[2];
        a3 += wv[k] * tp[3];
        a4 += wv[k] * tp[4];
    }
    #pragma unroll
    for (int off = 16; off > 0; off >>= 1) {
        a0 += __shfl_xor_sync(0xFFFFFFFFu, a0, off);
        a1 += __shfl_xor_sync(0xFFFFFFFFu, a1, off);
        a2 += __shfl_xor_sync(0xFFFFFFFFu, a2, off);
        a3 += __shfl_xor_sync(0xFFFFFFFFu, a3, off);
        a4 += __shfl_xor_sync(0xFFFFFFFFu, a4, off);
    }
    if (lane == 0) {
        float* pp = &partial[w * NB];
        pp[0] = a0; pp[1] = a1; pp[2] = a2; pp[3] = a3; pp[4] = a4;
    }
    __syncthreads();

    if (tid < NB) {
        float s = 0.f;
        #pragma unroll
        for (int q = 0; q < 8; q++) s += partial[q * NB + tid];
        v[tid] = s + b_ll[a] * g_S[tid] + b_fl[tid];
    }
    __syncthreads();

    float* base = out + ((size_t)(b * AVAL + a)) * (AVAL * NB);
    #pragma unroll
    for (int k = 0; k < 2; k++) {
        int idx = tid + k * 256;
        if (idx < AVAL * NB) base[idx] = v[idx % NB];
    }
}

// ---------------------------------------------------------------------------
extern "C" void kernel_launch(void* const* d_in, const int* in_sizes, int n_in,
                              void* d_out, int out_size) {
    const float* e    = (const float*)d_in[0];
    const float* W_ll = (const float*)d_in[1];
    const float* b_ll = (const float*)d_in[2];
    const float* W_fl = (const float*)d_in[3];
    const float* b_fl = (const float*)d_in[4];
    float* out = (float*)d_out;

    t_kernel<<<K1GRID, 256>>>(e, W_fl);
    out_kernel<<<dim3(AVAL, BVAL), 256>>>(W_ll, b_ll, b_fl, out);
}

// round 13
// speedup vs baseline: 2.0000x; 2.0000x over previous
#include <cuda_runtime.h>

// B=8, MSP=2048, D=512, A=64, NB=5
// Exact contraction reordering:
//   Wc[n,d]   = W_fl[n,d] + W_fl[n,512+d]
//   S[n]      = sum_d Wc[n,d]
//   t[b,s,n]  = sum_d e[b,s,d] * Wc[n,d]    (stored transposed g_tT[n][row])
//   out[b,a,n]= sum_s W_ll[a,s] * t[b,s,n] + b_ll[a]*S[n] + b_fl[n]
//   final[b,i,j,n] = out[b,i,n]
//
// R6's t_kernel (best measured t: 192thr, FFMA2, Wc in regs, depth-1
// prefetch, transposed store) + R5's out_kernel shape (512 blocks, best
// measured) with coalesced transposed t reads (fixes R5's 5-line gathers).

#define NROWS  16384      // B * MSP
#define DVAL   512
#define NB     5
#define AVAL   64
#define BVAL   8
#define MSP    2048

__device__ float g_S[NB];
__device__ float g_tT[NB * NROWS];         // transposed scratch, 320 KB

// Packed f32x2 FMA (Blackwell)
__device__ __forceinline__ unsigned long long fma2(unsigned long long a,
                                                   unsigned long long b,
                                                   unsigned long long c) {
    unsigned long long d;
    asm("fma.rn.f32x2 %0, %1, %2, %3;" : "=l"(d) : "l"(a), "l"(b), "l"(c));
    return d;
}
__device__ __forceinline__ float unpack_add(unsigned long long v) {
    float lo, hi;
    asm("mov.b64 {%0, %1}, %2;" : "=f"(lo), "=f"(hi) : "l"(v));
    return lo + hi;
}

// ---------------------------------------------------------------------------
// Kernel 1: t (R6 verbatim). 296 blocks x 192 threads, 2 blocks/SM.
// ---------------------------------------------------------------------------
__global__ __launch_bounds__(192, 2) void t_kernel(const float* __restrict__ e,
                                                   const float* __restrict__ W_fl) {
    __shared__ __align__(16) float wcs[NB * DVAL];   // 10 KB
    const int tid  = threadIdx.x;
    const int lane = tid & 31;
    const int warp = tid >> 5;

    for (int i = tid; i < NB * DVAL; i += 192) {
        int n = i / DVAL, d = i - n * DVAL;
        wcs[i] = W_fl[n * 1024 + d] + W_fl[n * 1024 + 512 + d];
    }
    __syncthreads();

    if (blockIdx.x == 0 && warp == 0) {
        #pragma unroll
        for (int n = 0; n < NB; n++) {
            float s = 0.f;
            for (int d = lane; d < DVAL; d += 32) s += wcs[n * DVAL + d];
            #pragma unroll
            for (int off = 16; off > 0; off >>= 1)
                s += __shfl_xor_sync(0xFFFFFFFFu, s, off);
            if (lane == 0) g_S[n] = s;
        }
    }

    // Per-lane Wc as packed f32x2 pairs: lane owns d = r*128 + lane*4 .. +3
    ulonglong2 wc2[4][NB];
    #pragma unroll
    for (int r = 0; r < 4; r++)
        #pragma unroll
        for (int n = 0; n < NB; n++)
            wc2[r][n] = *(const ulonglong2*)&wcs[n * DVAL + r * 128 + lane * 4];

    const int gw = blockIdx.x * 6 + warp;
    const int nw = 296 * 6;

    int row = gw;
    ulonglong2 ev[4];
    if (row < NROWS) {
        const ulonglong2* er = (const ulonglong2*)(e + (size_t)row * DVAL);
        #pragma unroll
        for (int r = 0; r < 4; r++) ev[r] = er[r * 32 + lane];
    }

    while (row < NROWS) {
        const int nxt = row + nw;

        ulonglong2 ev2[4];
        if (nxt < NROWS) {
            const ulonglong2* er2 = (const ulonglong2*)(e + (size_t)nxt * DVAL);
            #pragma unroll
            for (int r = 0; r < 4; r++) ev2[r] = er2[r * 32 + lane];
        }

        unsigned long long acc2[NB];
        #pragma unroll
        for (int n = 0; n < NB; n++) acc2[n] = 0ull;

        #pragma unroll
        for (int r = 0; r < 4; r++) {
            #pragma unroll
            for (int n = 0; n < NB; n++) {
                acc2[n] = fma2(ev[r].x, wc2[r][n].x, acc2[n]);
                acc2[n] = fma2(ev[r].y, wc2[r][n].y, acc2[n]);
            }
        }

        float acc[NB];
        #pragma unroll
        for (int n = 0; n < NB; n++) acc[n] = unpack_add(acc2[n]);

        #pragma unroll
        for (int n = 0; n < NB; n++) {
            #pragma unroll
            for (int off = 16; off > 0; off >>= 1)
                acc[n] += __shfl_xor_sync(0xFFFFFFFFu, acc[n], off);
        }

        // Transposed store: lane n writes g_tT[n][row]
        if (lane < NB) {
            float v = (lane == 0) ? acc[0] : (lane == 1) ? acc[1] :
                      (lane == 2) ? acc[2] : (lane == 3) ? acc[3] : acc[4];
            g_tT[lane * NROWS + row] = v;
        }

        #pragma unroll
        for (int r = 0; r < 4; r++) ev[r] = ev2[r];
        row = nxt;
    }
}

// ---------------------------------------------------------------------------
// Kernel 2: out + broadcast. R5 shape (grid 512 = (64 a, 8 b), 256 thr,
// 8 warps x 256-s chunks) with COALESCED transposed t reads, all 48 loads
// front-batched per thread.
// ---------------------------------------------------------------------------
__global__ __launch_bounds__(256) void out_kernel(const float* __restrict__ W_ll,
                                                  const float* __restrict__ b_ll,
                                                  const float* __restrict__ b_fl,
                                                  float* __restrict__ out) {
    __shared__ float partial[8 * NB];
    __shared__ float v[NB];
    const int a    = blockIdx.x;
    const int b    = blockIdx.y;
    const int tid  = threadIdx.x;
    const int lane = tid & 31;
    const int w    = tid >> 5;
    const int sb   = w * 256;

    // Front-batch: 8 W_ll + 40 t loads, all coalesced, all L2-resident.
    const float* wrow = W_ll + (size_t)a * MSP + sb;
    float wv[8];
    #pragma unroll
    for (int k = 0; k < 8; k++) wv[k] = wrow[lane + 32 * k];

    float tv[NB][8];
    #pragma unroll
    for (int n = 0; n < NB; n++) {
        const float* tp = g_tT + (size_t)n * NROWS + (size_t)b * MSP + sb;
        #pragma unroll
        for (int k = 0; k < 8; k++) tv[n][k] = tp[lane + 32 * k];
    }

    float a0 = 0.f, a1 = 0.f, a2 = 0.f, a3 = 0.f, a4 = 0.f;
    #pragma unroll
    for (int k = 0; k < 8; k++) {
        a0 += wv[k] * tv[0][k];
        a1 += wv[k] * tv[1][k];
        a2 += wv[k] * tv[2][k];
        a3 += wv[k] * tv[3][k];
        a4 += wv[k] * tv[4][k];
    }
    #pragma unroll
    for (int off = 16; off > 0; off >>= 1) {
        a0 += __shfl_xor_sync(0xFFFFFFFFu, a0, off);
        a1 += __shfl_xor_sync(0xFFFFFFFFu, a1, off);
        a2 += __shfl_xor_sync(0xFFFFFFFFu, a2, off);
        a3 += __shfl_xor_sync(0xFFFFFFFFu, a3, off);
        a4 += __shfl_xor_sync(0xFFFFFFFFu, a4, off);
    }
    if (lane == 0) {
        float* pp = &partial[w * NB];
        pp[0] = a0; pp[1] = a1; pp[2] = a2; pp[3] = a3; pp[4] = a4;
    }
    __syncthreads();

    if (tid < NB) {
        float s = 0.f;
        #pragma unroll
        for (int q = 0; q < 8; q++) s += partial[q * NB + tid];
        v[tid] = s + b_ll[a] * g_S[tid] + b_fl[tid];
    }
    __syncthreads();

    // Broadcast over j: 64 * 5 = 320 contiguous floats for this (b,a)
    float* base = out + ((size_t)(b * AVAL + a)) * (AVAL * NB);
    #pragma unroll
    for (int k = 0; k < 2; k++) {
        int idx = tid + k * 256;
        if (idx < AVAL * NB) base[idx] = v[idx % NB];
    }
}

// ---------------------------------------------------------------------------
extern "C" void kernel_launch(void* const* d_in, const int* in_sizes, int n_in,
                              void* d_out, int out_size) {
    const float* e    = (const float*)d_in[0];
    const float* W_ll = (const float*)d_in[1];
    const float* b_ll = (const float*)d_in[2];
    const float* W_fl = (const float*)d_in[3];
    const float* b_fl = (const float*)d_in[4];
    float* out = (float*)d_out;

    t_kernel<<<296, 192>>>(e, W_fl);
    out_kernel<<<dim3(AVAL, BVAL), 256>>>(W_ll, b_ll, b_fl, out);
}

// round 15
// speedup vs baseline: 2.0936x; 1.0468x over previous
#include <cuda_runtime.h>

// [Resubmission of R14 — previous round failed in infrastructure, never ran.]
//
// B=8, MSP=2048, D=512, A=64, NB=5
// Exact contraction reordering:
//   Wc[n,d]   = W_fl[n,d] + W_fl[n,512+d]
//   S[n]      = sum_d Wc[n,d]
//   t[b,s,n]  = sum_d e[b,s,d] * Wc[n,d]
//   out[b,a,n]= sum_s W_ll[a,s] * t[b,s,n] + b_ll[a]*S[n] + b_fl[n]
//   final[b,i,j,n] = out[b,i,n]
//
// t_kernel: 192 thr x 296 blocks (2/SM), FFMA2, Wc in 80 regs, TWO
// interleaved row streams per warp (static buffers evA/evB, reload issued
// before each SHFL tail) -> ~2-3 rows in flight per warp at all times.
// out_kernel: R5 verbatim (best measured).

#define NROWS  16384      // B * MSP
#define DVAL   512
#define NB     5
#define AVAL   64
#define BVAL   8
#define MSP    2048
#define NWARPT (296 * 6)  // t_kernel warps

__device__ float g_S[NB];
__device__ float g_t[NROWS * NB];          // 320 KB scratch

// Packed f32x2 FMA (Blackwell)
__device__ __forceinline__ unsigned long long fma2(unsigned long long a,
                                                   unsigned long long b,
                                                   unsigned long long c) {
    unsigned long long d;
    asm("fma.rn.f32x2 %0, %1, %2, %3;" : "=l"(d) : "l"(a), "l"(b), "l"(c));
    return d;
}
__device__ __forceinline__ float unpack_add(unsigned long long v) {
    float lo, hi;
    asm("mov.b64 {%0, %1}, %2;" : "=f"(lo), "=f"(hi) : "l"(v));
    return lo + hi;
}

__device__ __forceinline__ void load_row(ulonglong2 (&ev)[4],
                                         const float* __restrict__ e,
                                         int row, int lane) {
    const ulonglong2* er = (const ulonglong2*)(e + (size_t)row * DVAL);
    ev[0] = er[lane];
    ev[1] = er[32 + lane];
    ev[2] = er[64 + lane];
    ev[3] = er[96 + lane];
}

// FFMA2 inner product against register-resident Wc
__device__ __forceinline__ void dot_row(float (&t)[NB],
                                        const ulonglong2 (&ev)[4],
                                        const ulonglong2 (&wc2)[4][NB]) {
    unsigned long long acc2[NB];
    #pragma unroll
    for (int n = 0; n < NB; n++) acc2[n] = 0ull;
    #pragma unroll
    for (int r = 0; r < 4; r++) {
        #pragma unroll
        for (int n = 0; n < NB; n++) {
            acc2[n] = fma2(ev[r].x, wc2[r][n].x, acc2[n]);
            acc2[n] = fma2(ev[r].y, wc2[r][n].y, acc2[n]);
        }
    }
    #pragma unroll
    for (int n = 0; n < NB; n++) t[n] = unpack_add(acc2[n]);
}

__device__ __forceinline__ void reduce_store(float (&t)[NB], int row, int lane) {
    #pragma unroll
    for (int n = 0; n < NB; n++) {
        #pragma unroll
        for (int off = 16; off > 0; off >>= 1)
            t[n] += __shfl_xor_sync(0xFFFFFFFFu, t[n], off);
    }
    if (lane == 0) {
        float* tp = &g_t[row * NB];
        #pragma unroll
        for (int n = 0; n < NB; n++) tp[n] = t[n];
    }
}

// ---------------------------------------------------------------------------
// Kernel 1: t. 296 blocks x 192 threads (2 blocks/SM). Two row streams/warp.
// ---------------------------------------------------------------------------
__global__ __launch_bounds__(192, 2) void t_kernel(const float* __restrict__ e,
                                                   const float* __restrict__ W_fl) {
    __shared__ __align__(16) float wcs[NB * DVAL];   // 10 KB
    const int tid  = threadIdx.x;
    const int lane = tid & 31;
    const int warp = tid >> 5;

    for (int i = tid; i < NB * DVAL; i += 192) {
        int n = i / DVAL, d = i - n * DVAL;
        wcs[i] = W_fl[n * 1024 + d] + W_fl[n * 1024 + 512 + d];
    }
    __syncthreads();

    if (blockIdx.x == 0 && warp == 0) {
        #pragma unroll
        for (int n = 0; n < NB; n++) {
            float s = 0.f;
            for (int d = lane; d < DVAL; d += 32) s += wcs[n * DVAL + d];
            #pragma unroll
            for (int off = 16; off > 0; off >>= 1)
                s += __shfl_xor_sync(0xFFFFFFFFu, s, off);
            if (lane == 0) g_S[n] = s;
        }
    }

    // Per-lane Wc as packed f32x2 pairs: lane owns d = r*128 + lane*4 .. +3
    ulonglong2 wc2[4][NB];
    #pragma unroll
    for (int r = 0; r < 4; r++)
        #pragma unroll
        for (int n = 0; n < NB; n++)
            wc2[r][n] = *(const ulonglong2*)&wcs[n * DVAL + r * 128 + lane * 4];

    const int gw = blockIdx.x * 6 + warp;

    int rowA = gw;
    int rowB = gw + NWARPT;
    ulonglong2 evA[4], evB[4];
    if (rowA < NROWS) load_row(evA, e, rowA, lane);
    if (rowB < NROWS) load_row(evB, e, rowB, lane);

    while (rowA < NROWS) {
        // ---- stream A: consume, reload BEFORE the SHFL tail ----
        {
            float t[NB];
            dot_row(t, evA, wc2);
            const int nA = rowA + 2 * NWARPT;
            if (nA < NROWS) load_row(evA, e, nA, lane);
            reduce_store(t, rowA, lane);
            rowA = nA;
        }
        // ---- stream B ----
        if (rowB < NROWS) {
            float t[NB];
            dot_row(t, evB, wc2);
            const int nB = rowB + 2 * NWARPT;
            if (nB < NROWS) load_row(evB, e, nB, lane);
            reduce_store(t, rowB, lane);
            rowB = nB;
        }
    }
}

// ---------------------------------------------------------------------------
// Kernel 2: out + broadcast (R5 verbatim — best measured 6.6us).
// grid = (64 a, 8 b) = 512 blocks, 256 threads.
// ---------------------------------------------------------------------------
__global__ __launch_bounds__(256) void out_kernel(const float* __restrict__ W_ll,
                                                  const float* __restrict__ b_ll,
                                                  const float* __restrict__ b_fl,
                                                  float* __restrict__ out) {
    __shared__ float partial[8 * NB];
    __shared__ float v[NB];
    const int a    = blockIdx.x;
    const int b    = blockIdx.y;
    const int tid  = threadIdx.x;
    const int lane = tid & 31;
    const int w    = tid >> 5;

    const float* wrow  = W_ll + (size_t)a * MSP + w * 256;
    const float* tbase = g_t + ((size_t)b * MSP + w * 256) * NB;

    float wv[8];
    #pragma unroll
    for (int k = 0; k < 8; k++) wv[k] = wrow[lane + 32 * k];

    float a0 = 0.f, a1 = 0.f, a2 = 0.f, a3 = 0.f, a4 = 0.f;
    #pragma unroll
    for (int k = 0; k < 8; k++) {
        const float* tp = &tbase[(lane + 32 * k) * NB];
        a0 += wv[k] * tp[0];
        a1 += wv[k] * tp[1];
        a2 += wv[k] * tp[2];
        a3 += wv[k] * tp[3];
        a4 += wv[k] * tp[4];
    }
    #pragma unroll
    for (int off = 16; off > 0; off >>= 1) {
        a0 += __shfl_xor_sync(0xFFFFFFFFu, a0, off);
        a1 += __shfl_xor_sync(0xFFFFFFFFu, a1, off);
        a2 += __shfl_xor_sync(0xFFFFFFFFu, a2, off);
        a3 += __shfl_xor_sync(0xFFFFFFFFu, a3, off);
        a4 += __shfl_xor_sync(0xFFFFFFFFu, a4, off);
    }
    if (lane == 0) {
        float* pp = &partial[w * NB];
        pp[0] = a0; pp[1] = a1; pp[2] = a2; pp[3] = a3; pp[4] = a4;
    }
    __syncthreads();

    if (tid < NB) {
        float s = 0.f;
        #pragma unroll
        for (int q = 0; q < 8; q++) s += partial[q * NB + tid];
        v[tid] = s + b_ll[a] * g_S[tid] + b_fl[tid];
    }
    __syncthreads();

    float* base = out + ((size_t)(b * AVAL + a)) * (AVAL * NB);
    #pragma unroll
    for (int k = 0; k < 2; k++) {
        int idx = tid + k * 256;
        if (idx < AVAL * NB) base[idx] = v[idx % NB];
    }
}

// ---------------------------------------------------------------------------
extern "C" void kernel_launch(void* const* d_in, const int* in_sizes, int n_in,
                              void* d_out, int out_size) {
    const float* e    = (const float*)d_in[0];
    const float* W_ll = (const float*)d_in[1];
    const float* b_ll = (const float*)d_in[2];
    const float* W_fl = (const float*)d_in[3];
    const float* b_fl = (const float*)d_in[4];
    float* out = (float*)d_out;

    t_kernel<<<296, 192>>>(e, W_fl);
    out_kernel<<<dim3(AVAL, BVAL), 256>>>(W_ll, b_ll, b_fl, out);
}